// round 5
// baseline (speedup 1.0000x reference)
#include <cuda_runtime.h>

#define NN 20000
#define EE 640000
#define HH 128
#define EPS_BN   1e-5f
#define EPS_NORM 1e-6f
#define CACHE_ROWS 80

// ---------------- scratch (static __device__: allocation-free) ----------------
__device__ int   g_is64;
__device__ int   g_src32[EE];
__device__ int   g_dst32[EE];
__device__ int   g_deg[NN];
__device__ int   g_rowptr[NN + 1];
__device__ int   g_cursor[NN];
__device__ int   g_eidx[EE];
__device__ float g_A[NN * HH];   // nf @ Wg[:, 0:H].T   + bg
__device__ float g_B[NN * HH];   // nf @ Wg[:, H:2H].T
__device__ float g_D[NN * HH];   // nf @ Wd.T + bd
__device__ float g_S[NN * HH];   // nf @ Ws.T + bs
__device__ float g_h[NN * HH];   // pre-BN node update
__device__ float g_stats[4 * HH];   // [sumZ, sumsqZ | sumN, sumsqN]
__device__ float g_scale[4 * HH];   // [scaleZ, shiftZ | scaleN, shiftN]

__device__ __forceinline__ float fsigmoid(float x) { return 1.f / (1.f + __expf(-x)); }
__device__ __forceinline__ float fsilu(float x)    { return x / (1.f + __expf(-x)); }

// ---- packed f32x2 helpers (Blackwell FFMA2: 2 FMAs per instruction) ----
__device__ __forceinline__ void fma2(unsigned long long &d, unsigned long long a, unsigned long long b) {
    asm("fma.rn.f32x2 %0, %1, %2, %0;" : "+l"(d) : "l"(a), "l"(b));
}
__device__ __forceinline__ unsigned long long pack2(float x, float y) {
    unsigned long long r; asm("mov.b64 %0, {%1, %2};" : "=l"(r) : "f"(x), "f"(y)); return r;
}
__device__ __forceinline__ float2 unpack2(unsigned long long v) {
    float2 r; asm("mov.b64 {%0, %1}, %2;" : "=f"(r.x), "=f"(r.y) : "l"(v)); return r;
}

// ---------------- dtype detection: int64 vs int32 edge_index ----------------
__global__ void k_detect(const int* __restrict__ p) {
    __shared__ int nz;
    if (threadIdx.x == 0) nz = 0;
    __syncthreads();
    int bad = 0;
    for (int i = threadIdx.x; i < 4096; i += blockDim.x)
        if (p[2 * i + 1] != 0) bad = 1;
    if (bad) atomicExch(&nz, 1);
    __syncthreads();
    if (threadIdx.x == 0) g_is64 = (nz == 0) ? 1 : 0;
}

__global__ void k_zero() {
    int i = blockIdx.x * blockDim.x + threadIdx.x;
    if (i < NN)  g_deg[i] = 0;
    if (i < 4 * HH) g_stats[i] = 0.f;
}

// convert (int64->int32 if needed) + degree histogram, fused
__global__ void k_convert_hist(const void* __restrict__ eiv) {
    int e = blockIdx.x * blockDim.x + threadIdx.x;
    if (e >= EE) return;
    int s, d;
    if (g_is64) {
        const long long* p = (const long long*)eiv;
        s = (int)p[e]; d = (int)p[EE + e];
    } else {
        const int* p = (const int*)eiv;
        s = p[e]; d = p[EE + e];
    }
    g_src32[e] = s;
    g_dst32[e] = d;
    atomicAdd(&g_deg[s], 1);
}

__global__ void k_scan() {  // 1 block, 512 threads
    __shared__ int ssum[512];
    int t = threadIdx.x;
    const int CH = (NN + 511) / 512;
    int base = t * CH;
    int s = 0;
    for (int i = 0; i < CH; i++) {
        int idx = base + i;
        if (idx < NN) s += g_deg[idx];
    }
    ssum[t] = s;
    __syncthreads();
    for (int off = 1; off < 512; off <<= 1) {
        int v = (t >= off) ? ssum[t - off] : 0;
        __syncthreads();
        ssum[t] += v;
        __syncthreads();
    }
    int excl = (t == 0) ? 0 : ssum[t - 1];
    for (int i = 0; i < CH; i++) {
        int idx = base + i;
        if (idx < NN) {
            int d = g_deg[idx];
            g_rowptr[idx] = excl;
            g_cursor[idx] = excl;
            excl += d;
        }
    }
    if (t == 0) g_rowptr[NN] = ssum[511];
}

__global__ void k_scatter() {
    int e = blockIdx.x * blockDim.x + threadIdx.x;
    if (e >= EE) return;
    int p = atomicAdd(&g_cursor[g_src32[e]], 1);
    g_eidx[p] = e;
}

// ---------------- node GEMMs: A, B, D, S (blockIdx.y selects), f32x2 ----------------
__global__ __launch_bounds__(256) void k_node_gemm(
    const float* __restrict__ nf,
    const float* __restrict__ Wg, const float* __restrict__ bg,
    const float* __restrict__ Wd, const float* __restrict__ bd,
    const float* __restrict__ Ws, const float* __restrict__ bs)
{
    const float* W; const float* bias; float* out; int wstride, woff;
    switch (blockIdx.y) {
        case 0:  W = Wg; wstride = 3 * HH; woff = 0;  bias = bg; out = g_A; break;
        case 1:  W = Wg; wstride = 3 * HH; woff = HH; bias = 0;  out = g_B; break;
        case 2:  W = Wd; wstride = HH;     woff = 0;  bias = bd; out = g_D; break;
        default: W = Ws; wstride = HH;     woff = 0;  bias = bs; out = g_S; break;
    }
    __shared__ float sX[16][HH + 4];
    __shared__ float sW[16][HH + 4];
    int tid = threadIdx.x, tx = tid & 15, ty = tid >> 4;
    int bn = blockIdx.x * 128;
    unsigned long long acc2[8][4];
    #pragma unroll
    for (int i = 0; i < 8; i++)
        #pragma unroll
        for (int j = 0; j < 4; j++) acc2[i][j] = 0ULL;

    for (int k0 = 0; k0 < HH; k0 += 16) {
        #pragma unroll
        for (int l = 0; l < 2; l++) {
            int i = tid + l * 256;
            int r = i >> 2, kq = (i & 3) * 4;
            int gn = bn + r;
            float4 v = make_float4(0.f, 0.f, 0.f, 0.f);
            if (gn < NN) v = *(const float4*)&nf[gn * HH + k0 + kq];
            sX[kq + 0][r] = v.x; sX[kq + 1][r] = v.y; sX[kq + 2][r] = v.z; sX[kq + 3][r] = v.w;
            float4 w = *(const float4*)&W[r * wstride + woff + k0 + kq];
            sW[kq + 0][r] = w.x; sW[kq + 1][r] = w.y; sW[kq + 2][r] = w.z; sW[kq + 3][r] = w.w;
        }
        __syncthreads();
        #pragma unroll
        for (int k = 0; k < 16; k++) {
            float4 a0 = *(const float4*)&sX[k][ty * 4];
            float4 a1 = *(const float4*)&sX[k][64 + ty * 4];
            float4 b0 = *(const float4*)&sW[k][tx * 4];
            float4 b1 = *(const float4*)&sW[k][64 + tx * 4];
            unsigned long long bp[4] = {pack2(b0.x, b0.y), pack2(b0.z, b0.w),
                                        pack2(b1.x, b1.y), pack2(b1.z, b1.w)};
            float a[8] = {a0.x, a0.y, a0.z, a0.w, a1.x, a1.y, a1.z, a1.w};
            #pragma unroll
            for (int i = 0; i < 8; i++) {
                unsigned long long ap = pack2(a[i], a[i]);
                #pragma unroll
                for (int j = 0; j < 4; j++) fma2(acc2[i][j], ap, bp[j]);
            }
        }
        __syncthreads();
    }
    #pragma unroll
    for (int ih = 0; ih < 2; ih++)
        #pragma unroll
        for (int ii = 0; ii < 4; ii++) {
            int m = ih * 64 + ty * 4 + ii;
            int gn = bn + m;
            if (gn >= NN) continue;
            int ai = ih * 4 + ii;
            #pragma unroll
            for (int jh = 0; jh < 2; jh++) {
                int h = jh * 64 + tx * 4;
                float2 p0 = unpack2(acc2[ai][jh * 2 + 0]);
                float2 p1 = unpack2(acc2[ai][jh * 2 + 1]);
                float4 o = make_float4(p0.x, p0.y, p1.x, p1.y);
                if (bias) { o.x += bias[h]; o.y += bias[h + 1]; o.z += bias[h + 2]; o.w += bias[h + 3]; }
                *(float4*)&out[gn * HH + h] = o;
            }
        }
}

// ---- edge GEMM: lin[e] = ef[e] @ Wg3.T + A[src] + B[dst], f32x2 + fused BN stats ----
__global__ __launch_bounds__(256) void k_edge_gemm(
    const float* __restrict__ ef, const float* __restrict__ Wg,
    float* __restrict__ lin)
{
    __shared__ float sE[16][HH + 4];
    __shared__ float sW[16][HH + 4];
    __shared__ int sSrc[128], sDst[128];
    __shared__ float sRed[256];
    int tid = threadIdx.x, tx = tid & 15, ty = tid >> 4;
    int be = blockIdx.x * 128;
    if (tid < 128) { sSrc[tid] = g_src32[be + tid]; sDst[tid] = g_dst32[be + tid]; }
    sRed[tid] = 0.f;
    unsigned long long acc2[8][4];
    #pragma unroll
    for (int i = 0; i < 8; i++)
        #pragma unroll
        for (int j = 0; j < 4; j++) acc2[i][j] = 0ULL;

    for (int k0 = 0; k0 < HH; k0 += 16) {
        #pragma unroll
        for (int l = 0; l < 2; l++) {
            int i = tid + l * 256;
            int r = i >> 2, kq = (i & 3) * 4;
            float4 v = *(const float4*)&ef[(be + r) * HH + k0 + kq];
            sE[kq + 0][r] = v.x; sE[kq + 1][r] = v.y; sE[kq + 2][r] = v.z; sE[kq + 3][r] = v.w;
            float4 w = *(const float4*)&Wg[r * (3 * HH) + 2 * HH + k0 + kq];
            sW[kq + 0][r] = w.x; sW[kq + 1][r] = w.y; sW[kq + 2][r] = w.z; sW[kq + 3][r] = w.w;
        }
        __syncthreads();
        #pragma unroll
        for (int k = 0; k < 16; k++) {
            float4 a0 = *(const float4*)&sE[k][ty * 4];
            float4 a1 = *(const float4*)&sE[k][64 + ty * 4];
            float4 b0 = *(const float4*)&sW[k][tx * 4];
            float4 b1 = *(const float4*)&sW[k][64 + tx * 4];
            unsigned long long bp[4] = {pack2(b0.x, b0.y), pack2(b0.z, b0.w),
                                        pack2(b1.x, b1.y), pack2(b1.z, b1.w)};
            float a[8] = {a0.x, a0.y, a0.z, a0.w, a1.x, a1.y, a1.z, a1.w};
            #pragma unroll
            for (int i = 0; i < 8; i++) {
                unsigned long long ap = pack2(a[i], a[i]);
                #pragma unroll
                for (int j = 0; j < 4; j++) fma2(acc2[i][j], ap, bp[j]);
            }
        }
        __syncthreads();
    }

    float cs[8], cq[8];
    #pragma unroll
    for (int j = 0; j < 8; j++) { cs[j] = 0.f; cq[j] = 0.f; }

    #pragma unroll
    for (int ih = 0; ih < 2; ih++)
        #pragma unroll
        for (int ii = 0; ii < 4; ii++) {
            int m = ih * 64 + ty * 4 + ii;
            int e = be + m;
            int s = sSrc[m], d = sDst[m];
            int ai = ih * 4 + ii;
            #pragma unroll
            for (int jh = 0; jh < 2; jh++) {
                int h = jh * 64 + tx * 4;
                float2 p0 = unpack2(acc2[ai][jh * 2 + 0]);
                float2 p1 = unpack2(acc2[ai][jh * 2 + 1]);
                float4 va = *(const float4*)&g_A[s * HH + h];
                float4 vb = *(const float4*)&g_B[d * HH + h];
                float4 o;
                o.x = p0.x + va.x + vb.x;
                o.y = p0.y + va.y + vb.y;
                o.z = p1.x + va.z + vb.z;
                o.w = p1.y + va.w + vb.w;
                *(float4*)&lin[e * HH + h] = o;
                int jb = jh * 4;
                cs[jb + 0] += o.x; cq[jb + 0] = fmaf(o.x, o.x, cq[jb + 0]);
                cs[jb + 1] += o.y; cq[jb + 1] = fmaf(o.y, o.y, cq[jb + 1]);
                cs[jb + 2] += o.z; cq[jb + 2] = fmaf(o.z, o.z, cq[jb + 2]);
                cs[jb + 3] += o.w; cq[jb + 3] = fmaf(o.w, o.w, cq[jb + 3]);
            }
        }
    // reduce column sums across the 16 ty-threads via shared atomics
    #pragma unroll
    for (int j = 0; j < 8; j++) {
        int col = (j >> 2) * 64 + tx * 4 + (j & 3);
        atomicAdd(&sRed[col], cs[j]);
    }
    __syncthreads();
    // second half: sumsq (reuse sRed after draining sums)
    if (tid < 256) {
        // flush sums to global first
        atomicAdd(&g_stats[tid & 127], (tid < 128) ? sRed[tid] : 0.f);
    }
    __syncthreads();
    sRed[tid] = 0.f;
    __syncthreads();
    #pragma unroll
    for (int j = 0; j < 8; j++) {
        int col = (j >> 2) * 64 + tx * 4 + (j & 3);
        atomicAdd(&sRed[col], cq[j]);
    }
    __syncthreads();
    if (tid < 128) atomicAdd(&g_stats[HH + tid], sRed[tid]);
}

// ---------------- per-channel batch stats for node pre-BN (g_h) ----------------
__global__ void k_stats_node() {
    int c = threadIdx.x;
    float s = 0.f, q = 0.f;
    for (int r = blockIdx.x; r < NN; r += gridDim.x) {
        float v = g_h[r * HH + c];
        s += v;
        q = fmaf(v, v, q);
    }
    atomicAdd(&g_stats[2 * HH + c], s);
    atomicAdd(&g_stats[3 * HH + c], q);
}

__global__ void k_finalize(int statsOff, int outOff,
                           const float* __restrict__ gamma,
                           const float* __restrict__ beta, float cnt) {
    int c = threadIdx.x;
    float mean = g_stats[statsOff + c] / cnt;
    float var  = g_stats[statsOff + HH + c] / cnt - mean * mean;
    float sc   = gamma[c] * rsqrtf(var + EPS_BN);
    g_scale[outOff + c]      = sc;
    g_scale[outOff + HH + c] = beta[c] - mean * sc;
}

// ---------------- in-place: ue = silu(bn(lin)) ----------------
__global__ void k_edge_bn(float* __restrict__ lin) {
    __shared__ float ssc[HH], ssh[HH];
    int t = threadIdx.x;
    if (t < HH) { ssc[t] = g_scale[t]; ssh[t] = g_scale[HH + t]; }
    __syncthreads();
    const int total = EE * (HH / 4);
    float4* p = (float4*)lin;
    for (int i = blockIdx.x * blockDim.x + t; i < total; i += gridDim.x * blockDim.x) {
        int cq = (i & 31) * 4;
        float4 v = p[i];
        v.x = fsilu(fmaf(v.x, ssc[cq + 0], ssh[cq + 0]));
        v.y = fsilu(fmaf(v.y, ssc[cq + 1], ssh[cq + 1]));
        v.z = fsilu(fmaf(v.z, ssc[cq + 2], ssh[cq + 2]));
        v.w = fsilu(fmaf(v.w, ssc[cq + 3], ssh[cq + 3]));
        p[i] = v;
    }
}

// ---- node-centric CSR pass with shared sigmoid cache (no atomics) ----
__global__ __launch_bounds__(128) void k_nodepass(const float* __restrict__ ue) {
    __shared__ float sSig[CACHE_ROWS][HH];
    __shared__ int sD[CACHE_ROWS];
    int n = blockIdx.x;
    int c = threadIdx.x;
    int b0 = g_rowptr[n], b1 = g_rowptr[n + 1];
    float agg = 0.f;
    for (int i = b0; i < b1; i++) {
        int e = g_eidx[i];
        float sg = fsigmoid(ue[e * HH + c]);
        int idx = i - b0;
        if (idx < CACHE_ROWS) {
            sSig[idx][c] = sg;
            if (c == 0) sD[idx] = g_dst32[e];
        }
        agg += sg;
    }
    __syncthreads();
    float inv = 1.f / (agg + EPS_NORM);
    float acc = 0.f;
    int deg = b1 - b0;
    int cap = deg < CACHE_ROWS ? deg : CACHE_ROWS;
    for (int i = 0; i < cap; i++)
        acc = fmaf(sSig[i][c], g_D[sD[i] * HH + c], acc);
    for (int i = b0 + CACHE_ROWS; i < b1; i++) {
        int e = g_eidx[i];
        acc = fmaf(fsigmoid(ue[e * HH + c]), g_D[g_dst32[e] * HH + c], acc);
    }
    g_h[n * HH + c] = g_S[n * HH + c] + acc * inv;
}

// ---------------- final node output: nf + silu(bn(h)) ----------------
__global__ void k_nodes_out(const float* __restrict__ nf, float* __restrict__ outN) {
    int i = blockIdx.x * blockDim.x + threadIdx.x;
    if (i >= NN * HH) return;
    int c = i & (HH - 1);
    float x = fmaf(g_h[i], g_scale[2 * HH + c], g_scale[3 * HH + c]);
    outN[i] = nf[i] + fsilu(x);
}

// ---------------- launch ----------------
extern "C" void kernel_launch(void* const* d_in, const int* in_sizes, int n_in,
                              void* d_out, int out_size) {
    const void*  ei = d_in[0];
    const float* nf = (const float*)d_in[1];
    const float* ef = (const float*)d_in[2];
    const float* Wg = (const float*)d_in[3];
    const float* bg = (const float*)d_in[4];
    const float* Ws = (const float*)d_in[5];
    const float* bs = (const float*)d_in[6];
    const float* Wd = (const float*)d_in[7];
    const float* bd = (const float*)d_in[8];
    const float* zg = (const float*)d_in[9];
    const float* zb = (const float*)d_in[10];
    const float* ng = (const float*)d_in[11];
    const float* nb = (const float*)d_in[12];

    float* outN = (float*)d_out;            // [N, H] updated_nodes
    float* lin  = outN + (size_t)NN * HH;   // [E, H] lin -> updated_edge (in place)

    k_detect<<<1, 256>>>((const int*)ei);
    k_zero<<<(NN + 255) / 256, 256>>>();
    k_convert_hist<<<(EE + 255) / 256, 256>>>(ei);
    k_scan<<<1, 512>>>();
    k_scatter<<<(EE + 255) / 256, 256>>>();
    k_node_gemm<<<dim3((NN + 127) / 128, 4), 256>>>(nf, Wg, bg, Wd, bd, Ws, bs);
    k_edge_gemm<<<EE / 128, 256>>>(ef, Wg, lin);
    k_finalize<<<1, 128>>>(0, 0, zg, zb, (float)EE);
    k_edge_bn<<<2048, 256>>>(lin);
    k_nodepass<<<NN, 128>>>(lin);
    k_stats_node<<<2048, 128>>>();
    k_finalize<<<1, 128>>>(2 * HH, 2 * HH, ng, nb, (float)NN);
    k_nodes_out<<<(NN * HH + 255) / 256, 256>>>(nf, outN);
}

// round 7
// speedup vs baseline: 1.1081x; 1.1081x over previous
#include <cuda_runtime.h>
#include <cuda_bf16.h>
#include <cstdint>

#define NN 20000
#define EE 640000
#define HH 128
#define EPS_BN   1e-5f
#define EPS_NORM 1e-6f

// ---------------- scratch (static __device__: allocation-free) ----------------
__device__ int   g_is64;
__device__ int   g_src32[EE];
__device__ int   g_dst32[EE];
__device__ int   g_deg[NN];
__device__ int   g_rowptr[NN + 1];
__device__ int   g_cursor[NN];
__device__ int   g_eidx[EE];
__device__ float g_A[NN * HH];   // nf @ Wg[:, 0:H].T   + bg
__device__ float g_B[NN * HH];   // nf @ Wg[:, H:2H].T
__device__ float g_D[NN * HH];   // nf @ Wd.T + bd
__device__ float g_S[NN * HH];   // nf @ Ws.T + bs
__device__ float g_h[NN * HH];   // pre-BN node update
__device__ float g_stats[4 * HH];
__device__ float g_scale[4 * HH];
__device__ __nv_bfloat16 g_W3hi[HH * HH];  // [n][k] = Wg[n][2H+k] hi part
__device__ __nv_bfloat16 g_W3lo[HH * HH];  // lo residual

__device__ __forceinline__ float fsigmoid(float x) { return 1.f / (1.f + __expf(-x)); }
__device__ __forceinline__ float fsilu(float x)    { return x / (1.f + __expf(-x)); }

__device__ __forceinline__ uint32_t smem_u32(const void* p) {
    uint32_t a;
    asm("{ .reg .u64 t; cvta.to.shared.u64 t, %1; cvt.u32.u64 %0, t; }" : "=r"(a) : "l"(p));
    return a;
}

#define LDSM_X4(r0, r1, r2, r3, addr)                                              \
    asm volatile("ldmatrix.sync.aligned.m8n8.x4.shared.b16 {%0,%1,%2,%3}, [%4];"   \
        : "=r"(r0), "=r"(r1), "=r"(r2), "=r"(r3) : "r"(addr))

#define MMA_BF16(c, a, b)                                                          \
    asm volatile("mma.sync.aligned.m16n8k16.row.col.f32.bf16.bf16.f32 "            \
        "{%0,%1,%2,%3}, {%4,%5,%6,%7}, {%8,%9}, {%0,%1,%2,%3};"                    \
        : "+f"((c)[0]), "+f"((c)[1]), "+f"((c)[2]), "+f"((c)[3])                   \
        : "r"((a)[0]), "r"((a)[1]), "r"((a)[2]), "r"((a)[3]),                      \
          "r"((b)[0]), "r"((b)[1]))

// shared layout for HMMA edge kernel (bytes); stride 136 b16 per row
#define LDA 136
#define OFF_AHI 0
#define OFF_ALO 34816
#define OFF_BHI 69632
#define OFF_BLO 104448
#define SMEM_TOT 139264

__device__ __forceinline__ void cvt8(float4 a, float4 b, uint4 &hi, uint4 &lo) {
    float f[8] = {a.x, a.y, a.z, a.w, b.x, b.y, b.z, b.w};
    uint32_t hs[8], ls[8];
    #pragma unroll
    for (int i = 0; i < 8; i++) {
        __nv_bfloat16 h = __float2bfloat16(f[i]);
        hs[i] = (uint32_t)__bfloat16_as_ushort(h);
        __nv_bfloat16 l = __float2bfloat16(f[i] - __bfloat162float(h));
        ls[i] = (uint32_t)__bfloat16_as_ushort(l);
    }
    hi.x = hs[0] | (hs[1] << 16); hi.y = hs[2] | (hs[3] << 16);
    hi.z = hs[4] | (hs[5] << 16); hi.w = hs[6] | (hs[7] << 16);
    lo.x = ls[0] | (ls[1] << 16); lo.y = ls[2] | (ls[3] << 16);
    lo.z = ls[4] | (ls[5] << 16); lo.w = ls[6] | (ls[7] << 16);
}

// ---------------- dtype detection ----------------
__global__ void k_detect(const int* __restrict__ p) {
    __shared__ int nz;
    if (threadIdx.x == 0) nz = 0;
    __syncthreads();
    int bad = 0;
    for (int i = threadIdx.x; i < 4096; i += blockDim.x)
        if (p[2 * i + 1] != 0) bad = 1;
    if (bad) atomicExch(&nz, 1);
    __syncthreads();
    if (threadIdx.x == 0) g_is64 = (nz == 0) ? 1 : 0;
}

__global__ void k_zero() {
    int i = blockIdx.x * blockDim.x + threadIdx.x;
    if (i < NN)  g_deg[i] = 0;
    if (i < 4 * HH) g_stats[i] = 0.f;
}

__global__ void k_convert_hist(const void* __restrict__ eiv) {
    int e = blockIdx.x * blockDim.x + threadIdx.x;
    if (e >= EE) return;
    int s, d;
    if (g_is64) {
        const long long* p = (const long long*)eiv;
        s = (int)p[e]; d = (int)p[EE + e];
    } else {
        const int* p = (const int*)eiv;
        s = p[e]; d = p[EE + e];
    }
    g_src32[e] = s;
    g_dst32[e] = d;
    atomicAdd(&g_deg[s], 1);
}

__global__ void k_scan() {
    __shared__ int ssum[512];
    int t = threadIdx.x;
    const int CH = (NN + 511) / 512;
    int base = t * CH;
    int s = 0;
    for (int i = 0; i < CH; i++) {
        int idx = base + i;
        if (idx < NN) s += g_deg[idx];
    }
    ssum[t] = s;
    __syncthreads();
    for (int off = 1; off < 512; off <<= 1) {
        int v = (t >= off) ? ssum[t - off] : 0;
        __syncthreads();
        ssum[t] += v;
        __syncthreads();
    }
    int excl = (t == 0) ? 0 : ssum[t - 1];
    for (int i = 0; i < CH; i++) {
        int idx = base + i;
        if (idx < NN) {
            int d = g_deg[idx];
            g_rowptr[idx] = excl;
            g_cursor[idx] = excl;
            excl += d;
        }
    }
    if (t == 0) g_rowptr[NN] = ssum[511];
}

__global__ void k_scatter() {
    int e = blockIdx.x * blockDim.x + threadIdx.x;
    if (e >= EE) return;
    int p = atomicAdd(&g_cursor[g_src32[e]], 1);
    g_eidx[p] = e;
}

// ---------------- W3 hi/lo pre-split (once) ----------------
__global__ void k_wconv(const float* __restrict__ Wg) {
    int i = blockIdx.x * blockDim.x + threadIdx.x;
    if (i >= HH * HH) return;
    int n = i >> 7, k = i & 127;
    float v = Wg[n * 3 * HH + 2 * HH + k];
    __nv_bfloat16 h = __float2bfloat16(v);
    g_W3hi[i] = h;
    g_W3lo[i] = __float2bfloat16(v - __bfloat162float(h));
}

// ---------------- node GEMMs (R3 verified scalar) ----------------
__global__ __launch_bounds__(256) void k_node_gemm(
    const float* __restrict__ nf,
    const float* __restrict__ Wg, const float* __restrict__ bg,
    const float* __restrict__ Wd, const float* __restrict__ bd,
    const float* __restrict__ Ws, const float* __restrict__ bs)
{
    const float* W; const float* bias; float* out; int wstride, woff;
    switch (blockIdx.y) {
        case 0:  W = Wg; wstride = 3 * HH; woff = 0;  bias = bg; out = g_A; break;
        case 1:  W = Wg; wstride = 3 * HH; woff = HH; bias = 0;  out = g_B; break;
        case 2:  W = Wd; wstride = HH;     woff = 0;  bias = bd; out = g_D; break;
        default: W = Ws; wstride = HH;     woff = 0;  bias = bs; out = g_S; break;
    }
    __shared__ float sX[16][HH + 4];
    __shared__ float sW[16][HH + 4];
    int tid = threadIdx.x, tx = tid & 15, ty = tid >> 4;
    int bn = blockIdx.x * 128;
    float acc[8][8] = {};

    for (int k0 = 0; k0 < HH; k0 += 16) {
        #pragma unroll
        for (int l = 0; l < 2; l++) {
            int i = tid + l * 256;
            int r = i >> 2, kq = (i & 3) * 4;
            int gn = bn + r;
            float4 v = make_float4(0.f, 0.f, 0.f, 0.f);
            if (gn < NN) v = *(const float4*)&nf[gn * HH + k0 + kq];
            sX[kq + 0][r] = v.x; sX[kq + 1][r] = v.y; sX[kq + 2][r] = v.z; sX[kq + 3][r] = v.w;
            float4 w = *(const float4*)&W[r * wstride + woff + k0 + kq];
            sW[kq + 0][r] = w.x; sW[kq + 1][r] = w.y; sW[kq + 2][r] = w.z; sW[kq + 3][r] = w.w;
        }
        __syncthreads();
        #pragma unroll
        for (int k = 0; k < 16; k++) {
            float4 a0 = *(const float4*)&sX[k][ty * 4];
            float4 a1 = *(const float4*)&sX[k][64 + ty * 4];
            float4 b0 = *(const float4*)&sW[k][tx * 4];
            float4 b1 = *(const float4*)&sW[k][64 + tx * 4];
            float a[8] = {a0.x, a0.y, a0.z, a0.w, a1.x, a1.y, a1.z, a1.w};
            float b[8] = {b0.x, b0.y, b0.z, b0.w, b1.x, b1.y, b1.z, b1.w};
            #pragma unroll
            for (int i = 0; i < 8; i++)
                #pragma unroll
                for (int j = 0; j < 8; j++)
                    acc[i][j] = fmaf(a[i], b[j], acc[i][j]);
        }
        __syncthreads();
    }
    #pragma unroll
    for (int ih = 0; ih < 2; ih++)
        #pragma unroll
        for (int ii = 0; ii < 4; ii++) {
            int m = ih * 64 + ty * 4 + ii;
            int gn = bn + m;
            if (gn >= NN) continue;
            #pragma unroll
            for (int jh = 0; jh < 2; jh++) {
                int h = jh * 64 + tx * 4;
                float4 o;
                o.x = acc[ih * 4 + ii][jh * 4 + 0];
                o.y = acc[ih * 4 + ii][jh * 4 + 1];
                o.z = acc[ih * 4 + ii][jh * 4 + 2];
                o.w = acc[ih * 4 + ii][jh * 4 + 3];
                if (bias) { o.x += bias[h]; o.y += bias[h + 1]; o.z += bias[h + 2]; o.w += bias[h + 3]; }
                *(float4*)&out[gn * HH + h] = o;
            }
        }
}

// ---- edge GEMM via mma.sync bf16 3-term split ----
// lin[e] = ef[e] @ W3.T + A[src] + B[dst]; tile 128x128, K=128.
__global__ __launch_bounds__(256, 1) void k_edge_hmma(
    const float* __restrict__ ef, float* __restrict__ lin)
{
    extern __shared__ char smem[];
    uint32_t sb = smem_u32(smem);
    int tid = threadIdx.x, wid = tid >> 5, lid = tid & 31;
    int be = blockIdx.x * 128;
    int mi = wid & 3, ni = wid >> 2;   // warp tile: rows mi*32..+31, cols ni*64..+63

    // stage A (ef tile, bf16 hi/lo) and B (W3 hi/lo) into shared, k-contiguous
    for (int ch = tid; ch < 2048; ch += 256) {
        int r = ch >> 4, c8 = (ch & 15) << 3;
        uint32_t off = (uint32_t)(r * LDA + c8) * 2;
        {
            const float* p = &ef[(size_t)(be + r) * HH + c8];
            float4 v0 = *(const float4*)p, v1 = *(const float4*)(p + 4);
            uint4 hi, lo; cvt8(v0, v1, hi, lo);
            *(uint4*)(smem + OFF_AHI + off) = hi;
            *(uint4*)(smem + OFF_ALO + off) = lo;
        }
        {
            uint4 h = *(const uint4*)&g_W3hi[r * HH + c8];
            uint4 l = *(const uint4*)&g_W3lo[r * HH + c8];
            *(uint4*)(smem + OFF_BHI + off) = h;
            *(uint4*)(smem + OFF_BLO + off) = l;
        }
    }
    __syncthreads();

    float acc[2][8][4];
    #pragma unroll
    for (int i = 0; i < 2; i++)
        #pragma unroll
        for (int j = 0; j < 8; j++)
            #pragma unroll
            for (int q = 0; q < 4; q++) acc[i][j][q] = 0.f;

    // ldmatrix lane address components
    int aRowL = lid & 15, aColL = (lid >> 4) * 8;          // A: x4 (16 rows x 2 k-blocks)
    int bRowL = (lid & 7) + ((lid >> 4) & 1) * 8;          // B: x4 (2 n-tiles x 2 k-blocks)
    int bColL = ((lid >> 3) & 1) * 8;

    for (int k0 = 0; k0 < HH; k0 += 16) {
        uint32_t aHi[2][4], aLo[2][4], bHi[8][2], bLo[8][2];
        #pragma unroll
        for (int ti = 0; ti < 2; ti++) {
            int row = mi * 32 + ti * 16 + aRowL;
            uint32_t ad = sb + (uint32_t)((row * LDA + k0 + aColL) * 2);
            LDSM_X4(aHi[ti][0], aHi[ti][1], aHi[ti][2], aHi[ti][3], ad + OFF_AHI);
            LDSM_X4(aLo[ti][0], aLo[ti][1], aLo[ti][2], aLo[ti][3], ad + OFF_ALO);
        }
        #pragma unroll
        for (int p = 0; p < 4; p++) {      // pairs of n-tiles
            int n0 = ni * 64 + p * 16;
            uint32_t ad = sb + (uint32_t)(((n0 + bRowL) * LDA + k0 + bColL) * 2);
            uint32_t r0, r1, r2, r3;
            LDSM_X4(r0, r1, r2, r3, ad + OFF_BHI);
            bHi[p * 2][0] = r0; bHi[p * 2][1] = r1;
            bHi[p * 2 + 1][0] = r2; bHi[p * 2 + 1][1] = r3;
            LDSM_X4(r0, r1, r2, r3, ad + OFF_BLO);
            bLo[p * 2][0] = r0; bLo[p * 2][1] = r1;
            bLo[p * 2 + 1][0] = r2; bLo[p * 2 + 1][1] = r3;
        }
        #pragma unroll
        for (int ti = 0; ti < 2; ti++)
            #pragma unroll
            for (int tj = 0; tj < 8; tj++) {
                MMA_BF16(acc[ti][tj], aHi[ti], bHi[tj]);
                MMA_BF16(acc[ti][tj], aHi[ti], bLo[tj]);
                MMA_BF16(acc[ti][tj], aLo[ti], bHi[tj]);
            }
    }

    // epilogue: + A[src] + B[dst], write lin
    int g = lid >> 2, t2 = (lid & 3) * 2;
    #pragma unroll
    for (int ti = 0; ti < 2; ti++)
        #pragma unroll
        for (int rr = 0; rr < 2; rr++) {
            int row = mi * 32 + ti * 16 + rr * 8 + g;
            int e = be + row;
            int s = g_src32[e], d = g_dst32[e];
            const float* ar = &g_A[(size_t)s * HH];
            const float* br = &g_B[(size_t)d * HH];
            float* orow = &lin[(size_t)e * HH];
            #pragma unroll
            for (int tj = 0; tj < 8; tj++) {
                int c = ni * 64 + tj * 8 + t2;
                float2 av = *(const float2*)&ar[c];
                float2 bv = *(const float2*)&br[c];
                float2 o;
                o.x = acc[ti][tj][rr * 2 + 0] + av.x + bv.x;
                o.y = acc[ti][tj][rr * 2 + 1] + av.y + bv.y;
                *(float2*)&orow[c] = o;
            }
        }
}

// ---------------- per-channel batch stats ----------------
__global__ void k_stats(const float* __restrict__ xp, int rows, int statsOff, int useH) {
    const float* x = useH ? g_h : xp;
    int c = threadIdx.x;
    float s = 0.f, q = 0.f;
    for (int r = blockIdx.x; r < rows; r += gridDim.x) {
        float v = x[r * HH + c];
        s += v;
        q = fmaf(v, v, q);
    }
    atomicAdd(&g_stats[statsOff + c], s);
    atomicAdd(&g_stats[statsOff + HH + c], q);
}

__global__ void k_finalize(int statsOff, int outOff,
                           const float* __restrict__ gamma,
                           const float* __restrict__ beta, float cnt) {
    int c = threadIdx.x;
    float mean = g_stats[statsOff + c] / cnt;
    float var  = g_stats[statsOff + HH + c] / cnt - mean * mean;
    float sc   = gamma[c] * rsqrtf(var + EPS_BN);
    g_scale[outOff + c]      = sc;
    g_scale[outOff + HH + c] = beta[c] - mean * sc;
}

// ---------------- in-place: ue = silu(bn(lin)) ----------------
__global__ void k_edge_bn(float* __restrict__ lin) {
    __shared__ float ssc[HH], ssh[HH];
    int t = threadIdx.x;
    if (t < HH) { ssc[t] = g_scale[t]; ssh[t] = g_scale[HH + t]; }
    __syncthreads();
    const int total = EE * (HH / 4);
    float4* p = (float4*)lin;
    for (int i = blockIdx.x * blockDim.x + t; i < total; i += gridDim.x * blockDim.x) {
        int cq = (i & 31) * 4;
        float4 v = p[i];
        v.x = fsilu(fmaf(v.x, ssc[cq + 0], ssh[cq + 0]));
        v.y = fsilu(fmaf(v.y, ssc[cq + 1], ssh[cq + 1]));
        v.z = fsilu(fmaf(v.z, ssc[cq + 2], ssh[cq + 2]));
        v.w = fsilu(fmaf(v.w, ssc[cq + 3], ssh[cq + 3]));
        p[i] = v;
    }
}

// ---- node-centric CSR pass (R3 verified) ----
__global__ __launch_bounds__(128) void k_nodepass(const float* __restrict__ ue) {
    int n = blockIdx.x;
    int c = threadIdx.x;
    int b0 = g_rowptr[n], b1 = g_rowptr[n + 1];
    float agg = 0.f;
    for (int i = b0; i < b1; i++) {
        int e = g_eidx[i];
        agg += fsigmoid(ue[e * HH + c]);
    }
    float inv = 1.f / (agg + EPS_NORM);
    float acc = 0.f;
    for (int i = b0; i < b1; i++) {
        int e = g_eidx[i];
        int d = g_dst32[e];
        float sg = fsigmoid(ue[e * HH + c]);
        acc = fmaf(sg, g_D[d * HH + c], acc);
    }
    g_h[n * HH + c] = g_S[n * HH + c] + acc * inv;
}

// ---------------- final node output ----------------
__global__ void k_nodes_out(const float* __restrict__ nf, float* __restrict__ outN) {
    int i = blockIdx.x * blockDim.x + threadIdx.x;
    if (i >= NN * HH) return;
    int c = i & (HH - 1);
    float x = fmaf(g_h[i], g_scale[2 * HH + c], g_scale[3 * HH + c]);
    outN[i] = nf[i] + fsilu(x);
}

// ---------------- launch ----------------
extern "C" void kernel_launch(void* const* d_in, const int* in_sizes, int n_in,
                              void* d_out, int out_size) {
    const void*  ei = d_in[0];
    const float* nf = (const float*)d_in[1];
    const float* ef = (const float*)d_in[2];
    const float* Wg = (const float*)d_in[3];
    const float* bg = (const float*)d_in[4];
    const float* Ws = (const float*)d_in[5];
    const float* bs = (const float*)d_in[6];
    const float* Wd = (const float*)d_in[7];
    const float* bd = (const float*)d_in[8];
    const float* zg = (const float*)d_in[9];
    const float* zb = (const float*)d_in[10];
    const float* ng = (const float*)d_in[11];
    const float* nb = (const float*)d_in[12];

    float* outN = (float*)d_out;            // [N, H] updated_nodes
    float* lin  = outN + (size_t)NN * HH;   // [E, H] lin -> updated_edge (in place)

    static int s_attr_done = 0;
    if (!s_attr_done) {
        cudaFuncSetAttribute(k_edge_hmma, cudaFuncAttributeMaxDynamicSharedMemorySize, SMEM_TOT);
        s_attr_done = 1;
    }

    k_detect<<<1, 256>>>((const int*)ei);
    k_zero<<<(NN + 255) / 256, 256>>>();
    k_convert_hist<<<(EE + 255) / 256, 256>>>(ei);
    k_scan<<<1, 512>>>();
    k_scatter<<<(EE + 255) / 256, 256>>>();
    k_wconv<<<(HH * HH + 255) / 256, 256>>>(Wg);
    k_node_gemm<<<dim3((NN + 127) / 128, 4), 256>>>(nf, Wg, bg, Wd, bd, Ws, bs);
    k_edge_hmma<<<EE / 128, 256, SMEM_TOT>>>(ef, lin);
    k_stats<<<2048, 128>>>(lin, EE, 0, 0);
    k_finalize<<<1, 128>>>(0, 0, zg, zb, (float)EE);
    k_edge_bn<<<2048, 256>>>(lin);
    k_nodepass<<<NN, 128>>>(lin);
    k_stats<<<2048, 128>>>(nullptr, NN, 2 * HH, 1);
    k_finalize<<<1, 128>>>(2 * HH, 2 * HH, ng, nb, (float)NN);
    k_nodes_out<<<(NN * HH + 255) / 256, 256>>>(nf, outN);
}

// round 8
// speedup vs baseline: 1.3040x; 1.1767x over previous
#include <cuda_runtime.h>
#include <cuda_bf16.h>
#include <cstdint>

#define NN 20000
#define EE 640000
#define HH 128
#define EPS_BN   1e-5f
#define EPS_NORM 1e-6f

// ---------------- scratch (static __device__: allocation-free) ----------------
__device__ int   g_is64;
__device__ int   g_src32[EE];
__device__ int   g_dst32[EE];
__device__ int   g_deg[NN];
__device__ int   g_rowptr[NN + 1];
__device__ int   g_cursor[NN];
__device__ int   g_eidx[EE];
__device__ float g_A[NN * HH];   // nf @ Wg[:, 0:H].T   + bg
__device__ float g_B[NN * HH];   // nf @ Wg[:, H:2H].T
__device__ float g_D[NN * HH];   // nf @ Wd.T + bd
__device__ float g_S[NN * HH];   // nf @ Ws.T + bs
__device__ float g_h[NN * HH];   // pre-BN node update
__device__ float g_stats[4 * HH];
__device__ float g_scale[4 * HH];
__device__ __nv_bfloat16 g_W3hi[HH * HH];  // [n][k] = Wg[n][2H+k] hi part
__device__ __nv_bfloat16 g_W3lo[HH * HH];  // lo residual

__device__ __forceinline__ float fsigmoid(float x) { return 1.f / (1.f + __expf(-x)); }
__device__ __forceinline__ float fsilu(float x)    { return x / (1.f + __expf(-x)); }

__device__ __forceinline__ uint32_t smem_u32(const void* p) {
    uint32_t a;
    asm("{ .reg .u64 t; cvta.to.shared.u64 t, %1; cvt.u32.u64 %0, t; }" : "=r"(a) : "l"(p));
    return a;
}

#define LDSM_X4(r0, r1, r2, r3, addr)                                              \
    asm volatile("ldmatrix.sync.aligned.m8n8.x4.shared.b16 {%0,%1,%2,%3}, [%4];"   \
        : "=r"(r0), "=r"(r1), "=r"(r2), "=r"(r3) : "r"(addr))

#define MMA_BF16(c, a, b)                                                          \
    asm volatile("mma.sync.aligned.m16n8k16.row.col.f32.bf16.bf16.f32 "            \
        "{%0,%1,%2,%3}, {%4,%5,%6,%7}, {%8,%9}, {%0,%1,%2,%3};"                    \
        : "+f"((c)[0]), "+f"((c)[1]), "+f"((c)[2]), "+f"((c)[3])                   \
        : "r"((a)[0]), "r"((a)[1]), "r"((a)[2]), "r"((a)[3]),                      \
          "r"((b)[0]), "r"((b)[1]))

// shared layout (bytes): k-half staging, stride 72 halves per row
#define LDA2 72
#define A_PANEL (64 * LDA2 * 2)     // 9216
#define B_PANEL (128 * LDA2 * 2)    // 18432
#define OFF_AHI 0
#define OFF_ALO (OFF_AHI + A_PANEL)
#define OFF_BHI (OFF_ALO + A_PANEL)
#define OFF_BLO (OFF_BHI + B_PANEL)
#define OFF_IDX (OFF_BLO + B_PANEL)
#define SMEM_TOT2 (OFF_IDX + 512)   // 55808

__device__ __forceinline__ void cvt8(float4 a, float4 b, uint4 &hi, uint4 &lo) {
    float f[8] = {a.x, a.y, a.z, a.w, b.x, b.y, b.z, b.w};
    uint32_t hs[8], ls[8];
    #pragma unroll
    for (int i = 0; i < 8; i++) {
        __nv_bfloat16 h = __float2bfloat16(f[i]);
        hs[i] = (uint32_t)__bfloat16_as_ushort(h);
        __nv_bfloat16 l = __float2bfloat16(f[i] - __bfloat162float(h));
        ls[i] = (uint32_t)__bfloat16_as_ushort(l);
    }
    hi.x = hs[0] | (hs[1] << 16); hi.y = hs[2] | (hs[3] << 16);
    hi.z = hs[4] | (hs[5] << 16); hi.w = hs[6] | (hs[7] << 16);
    lo.x = ls[0] | (ls[1] << 16); lo.y = ls[2] | (ls[3] << 16);
    lo.z = ls[4] | (ls[5] << 16); lo.w = ls[6] | (ls[7] << 16);
}

// ---------------- dtype detection ----------------
__global__ void k_detect(const int* __restrict__ p) {
    __shared__ int nz;
    if (threadIdx.x == 0) nz = 0;
    __syncthreads();
    int bad = 0;
    for (int i = threadIdx.x; i < 4096; i += blockDim.x)
        if (p[2 * i + 1] != 0) bad = 1;
    if (bad) atomicExch(&nz, 1);
    __syncthreads();
    if (threadIdx.x == 0) g_is64 = (nz == 0) ? 1 : 0;
}

__global__ void k_zero() {
    int i = blockIdx.x * blockDim.x + threadIdx.x;
    if (i < NN)  g_deg[i] = 0;
    if (i < 4 * HH) g_stats[i] = 0.f;
}

__global__ void k_convert_hist(const void* __restrict__ eiv) {
    int e = blockIdx.x * blockDim.x + threadIdx.x;
    if (e >= EE) return;
    int s, d;
    if (g_is64) {
        const long long* p = (const long long*)eiv;
        s = (int)p[e]; d = (int)p[EE + e];
    } else {
        const int* p = (const int*)eiv;
        s = p[e]; d = p[EE + e];
    }
    g_src32[e] = s;
    g_dst32[e] = d;
    atomicAdd(&g_deg[s], 1);
}

__global__ void k_scan() {
    __shared__ int ssum[512];
    int t = threadIdx.x;
    const int CH = (NN + 511) / 512;
    int base = t * CH;
    int s = 0;
    for (int i = 0; i < CH; i++) {
        int idx = base + i;
        if (idx < NN) s += g_deg[idx];
    }
    ssum[t] = s;
    __syncthreads();
    for (int off = 1; off < 512; off <<= 1) {
        int v = (t >= off) ? ssum[t - off] : 0;
        __syncthreads();
        ssum[t] += v;
        __syncthreads();
    }
    int excl = (t == 0) ? 0 : ssum[t - 1];
    for (int i = 0; i < CH; i++) {
        int idx = base + i;
        if (idx < NN) {
            int d = g_deg[idx];
            g_rowptr[idx] = excl;
            g_cursor[idx] = excl;
            excl += d;
        }
    }
    if (t == 0) g_rowptr[NN] = ssum[511];
}

__global__ void k_scatter() {
    int e = blockIdx.x * blockDim.x + threadIdx.x;
    if (e >= EE) return;
    int p = atomicAdd(&g_cursor[g_src32[e]], 1);
    g_eidx[p] = e;
}

// ---------------- W3 hi/lo pre-split (once) ----------------
__global__ void k_wconv(const float* __restrict__ Wg) {
    int i = blockIdx.x * blockDim.x + threadIdx.x;
    if (i >= HH * HH) return;
    int n = i >> 7, k = i & 127;
    float v = Wg[n * 3 * HH + 2 * HH + k];
    __nv_bfloat16 h = __float2bfloat16(v);
    g_W3hi[i] = h;
    g_W3lo[i] = __float2bfloat16(v - __bfloat162float(h));
}

// ---------------- node GEMMs (R3 verified scalar) ----------------
__global__ __launch_bounds__(256) void k_node_gemm(
    const float* __restrict__ nf,
    const float* __restrict__ Wg, const float* __restrict__ bg,
    const float* __restrict__ Wd, const float* __restrict__ bd,
    const float* __restrict__ Ws, const float* __restrict__ bs)
{
    const float* W; const float* bias; float* out; int wstride, woff;
    switch (blockIdx.y) {
        case 0:  W = Wg; wstride = 3 * HH; woff = 0;  bias = bg; out = g_A; break;
        case 1:  W = Wg; wstride = 3 * HH; woff = HH; bias = 0;  out = g_B; break;
        case 2:  W = Wd; wstride = HH;     woff = 0;  bias = bd; out = g_D; break;
        default: W = Ws; wstride = HH;     woff = 0;  bias = bs; out = g_S; break;
    }
    __shared__ float sX[16][HH + 4];
    __shared__ float sW[16][HH + 4];
    int tid = threadIdx.x, tx = tid & 15, ty = tid >> 4;
    int bn = blockIdx.x * 128;
    float acc[8][8] = {};

    for (int k0 = 0; k0 < HH; k0 += 16) {
        #pragma unroll
        for (int l = 0; l < 2; l++) {
            int i = tid + l * 256;
            int r = i >> 2, kq = (i & 3) * 4;
            int gn = bn + r;
            float4 v = make_float4(0.f, 0.f, 0.f, 0.f);
            if (gn < NN) v = *(const float4*)&nf[gn * HH + k0 + kq];
            sX[kq + 0][r] = v.x; sX[kq + 1][r] = v.y; sX[kq + 2][r] = v.z; sX[kq + 3][r] = v.w;
            float4 w = *(const float4*)&W[r * wstride + woff + k0 + kq];
            sW[kq + 0][r] = w.x; sW[kq + 1][r] = w.y; sW[kq + 2][r] = w.z; sW[kq + 3][r] = w.w;
        }
        __syncthreads();
        #pragma unroll
        for (int k = 0; k < 16; k++) {
            float4 a0 = *(const float4*)&sX[k][ty * 4];
            float4 a1 = *(const float4*)&sX[k][64 + ty * 4];
            float4 b0 = *(const float4*)&sW[k][tx * 4];
            float4 b1 = *(const float4*)&sW[k][64 + tx * 4];
            float a[8] = {a0.x, a0.y, a0.z, a0.w, a1.x, a1.y, a1.z, a1.w};
            float b[8] = {b0.x, b0.y, b0.z, b0.w, b1.x, b1.y, b1.z, b1.w};
            #pragma unroll
            for (int i = 0; i < 8; i++)
                #pragma unroll
                for (int j = 0; j < 8; j++)
                    acc[i][j] = fmaf(a[i], b[j], acc[i][j]);
        }
        __syncthreads();
    }
    #pragma unroll
    for (int ih = 0; ih < 2; ih++)
        #pragma unroll
        for (int ii = 0; ii < 4; ii++) {
            int m = ih * 64 + ty * 4 + ii;
            int gn = bn + m;
            if (gn >= NN) continue;
            #pragma unroll
            for (int jh = 0; jh < 2; jh++) {
                int h = jh * 64 + tx * 4;
                float4 o;
                o.x = acc[ih * 4 + ii][jh * 4 + 0];
                o.y = acc[ih * 4 + ii][jh * 4 + 1];
                o.z = acc[ih * 4 + ii][jh * 4 + 2];
                o.w = acc[ih * 4 + ii][jh * 4 + 3];
                if (bias) { o.x += bias[h]; o.y += bias[h + 1]; o.z += bias[h + 2]; o.w += bias[h + 3]; }
                *(float4*)&out[gn * HH + h] = o;
            }
        }
}

// ---- edge GEMM via mma.sync bf16 3-term split; tile 64x128, K staged 2x64 ----
// lin[e] = ef[e] @ W3.T + A[src] + B[dst]
__global__ __launch_bounds__(256, 2) void k_edge_hmma(
    const void* __restrict__ eiv, const float* __restrict__ ef,
    float* __restrict__ lin)
{
    extern __shared__ char smem[];
    uint32_t sb = smem_u32(smem);
    int tid = threadIdx.x, wid = tid >> 5, lid = tid & 31;
    int be = blockIdx.x * 64;
    int mi = wid & 1, ni = wid >> 1;    // warp tile: rows mi*32..+31, cols ni*32..+31

    // stage src/dst straight from raw edge_index
    if (tid < 64) {
        int e = be + tid;
        int s, d;
        if (g_is64) {
            const long long* p = (const long long*)eiv;
            s = (int)p[e]; d = (int)p[EE + e];
        } else {
            const int* p = (const int*)eiv;
            s = p[e]; d = p[EE + e];
        }
        ((int*)(smem + OFF_IDX))[tid] = s;
        ((int*)(smem + OFF_IDX))[64 + tid] = d;
    }

    float acc[2][4][4];
    #pragma unroll
    for (int i = 0; i < 2; i++)
        #pragma unroll
        for (int j = 0; j < 4; j++)
            #pragma unroll
            for (int q = 0; q < 4; q++) acc[i][j][q] = 0.f;

    int aRowL = lid & 15, aColL = (lid >> 4) * 8;
    int bRowL = (lid & 7) + ((lid >> 4) & 1) * 8;
    int bColL = ((lid >> 3) & 1) * 8;

    for (int kh = 0; kh < 2; kh++) {
        int kbase = kh * 64;
        // stage A: 64 rows x 64 cols fp32 -> bf16 hi/lo (each thread 16 floats)
        {
            int r = tid >> 2;
            int c8 = (tid & 3) * 16;
            const float* p = &ef[(size_t)(be + r) * HH + kbase + c8];
            float4 v0 = *(const float4*)p, v1 = *(const float4*)(p + 4);
            uint4 hi, lo; cvt8(v0, v1, hi, lo);
            uint32_t off = (uint32_t)(r * LDA2 + c8) * 2;
            *(uint4*)(smem + OFF_AHI + off) = hi;
            *(uint4*)(smem + OFF_ALO + off) = lo;
            v0 = *(const float4*)(p + 8); v1 = *(const float4*)(p + 12);
            cvt8(v0, v1, hi, lo);
            *(uint4*)(smem + OFF_AHI + off + 16) = hi;
            *(uint4*)(smem + OFF_ALO + off + 16) = lo;
        }
        // stage B: 128 rows x 64 cols bf16 from pre-split W3
        for (int i = tid; i < 1024; i += 256) {
            int r = i >> 3;
            int c8 = (i & 7) * 8;
            uint32_t off = (uint32_t)(r * LDA2 + c8) * 2;
            *(uint4*)(smem + OFF_BHI + off) = *(const uint4*)&g_W3hi[r * HH + kbase + c8];
            *(uint4*)(smem + OFF_BLO + off) = *(const uint4*)&g_W3lo[r * HH + kbase + c8];
        }
        __syncthreads();

        #pragma unroll
        for (int k0 = 0; k0 < 64; k0 += 16) {
            uint32_t aHi[2][4], aLo[2][4], bHi[4][2], bLo[4][2];
            #pragma unroll
            for (int ti = 0; ti < 2; ti++) {
                int row = mi * 32 + ti * 16 + aRowL;
                uint32_t ad = sb + (uint32_t)((row * LDA2 + k0 + aColL) * 2);
                LDSM_X4(aHi[ti][0], aHi[ti][1], aHi[ti][2], aHi[ti][3], ad + OFF_AHI);
                LDSM_X4(aLo[ti][0], aLo[ti][1], aLo[ti][2], aLo[ti][3], ad + OFF_ALO);
            }
            #pragma unroll
            for (int p = 0; p < 2; p++) {
                int n0 = ni * 32 + p * 16;
                uint32_t ad = sb + (uint32_t)(((n0 + bRowL) * LDA2 + k0 + bColL) * 2);
                uint32_t r0, r1, r2, r3;
                LDSM_X4(r0, r1, r2, r3, ad + OFF_BHI);
                bHi[p * 2][0] = r0; bHi[p * 2][1] = r1;
                bHi[p * 2 + 1][0] = r2; bHi[p * 2 + 1][1] = r3;
                LDSM_X4(r0, r1, r2, r3, ad + OFF_BLO);
                bLo[p * 2][0] = r0; bLo[p * 2][1] = r1;
                bLo[p * 2 + 1][0] = r2; bLo[p * 2 + 1][1] = r3;
            }
            #pragma unroll
            for (int ti = 0; ti < 2; ti++)
                #pragma unroll
                for (int tj = 0; tj < 4; tj++) {
                    MMA_BF16(acc[ti][tj], aHi[ti], bHi[tj]);
                    MMA_BF16(acc[ti][tj], aHi[ti], bLo[tj]);
                    MMA_BF16(acc[ti][tj], aLo[ti], bHi[tj]);
                }
        }
        __syncthreads();
    }

    // epilogue: + A[src] + B[dst]
    int g = lid >> 2, t2 = (lid & 3) * 2;
    const int* sIdx = (const int*)(smem + OFF_IDX);
    #pragma unroll
    for (int ti = 0; ti < 2; ti++)
        #pragma unroll
        for (int rr = 0; rr < 2; rr++) {
            int row = mi * 32 + ti * 16 + rr * 8 + g;
            int e = be + row;
            int s = sIdx[row], d = sIdx[64 + row];
            const float* ar = &g_A[(size_t)s * HH];
            const float* br = &g_B[(size_t)d * HH];
            float* orow = &lin[(size_t)e * HH];
            #pragma unroll
            for (int tj = 0; tj < 4; tj++) {
                int c = ni * 32 + tj * 8 + t2;
                float2 av = *(const float2*)&ar[c];
                float2 bv = *(const float2*)&br[c];
                float2 o;
                o.x = acc[ti][tj][rr * 2 + 0] + av.x + bv.x;
                o.y = acc[ti][tj][rr * 2 + 1] + av.y + bv.y;
                *(float2*)&orow[c] = o;
            }
        }
}

// ---------------- per-channel batch stats ----------------
__global__ void k_stats(const float* __restrict__ xp, int rows, int statsOff, int useH) {
    const float* x = useH ? g_h : xp;
    int c = threadIdx.x;
    float s = 0.f, q = 0.f;
    for (int r = blockIdx.x; r < rows; r += gridDim.x) {
        float v = x[r * HH + c];
        s += v;
        q = fmaf(v, v, q);
    }
    atomicAdd(&g_stats[statsOff + c], s);
    atomicAdd(&g_stats[statsOff + HH + c], q);
}

__global__ void k_finalize(int statsOff, int outOff,
                           const float* __restrict__ gamma,
                           const float* __restrict__ beta, float cnt) {
    int c = threadIdx.x;
    float mean = g_stats[statsOff + c] / cnt;
    float var  = g_stats[statsOff + HH + c] / cnt - mean * mean;
    float sc   = gamma[c] * rsqrtf(var + EPS_BN);
    g_scale[outOff + c]      = sc;
    g_scale[outOff + HH + c] = beta[c] - mean * sc;
}

// ---------------- in-place: ue = silu(bn(lin)) ----------------
__global__ void k_edge_bn(float* __restrict__ lin) {
    __shared__ float ssc[HH], ssh[HH];
    int t = threadIdx.x;
    if (t < HH) { ssc[t] = g_scale[t]; ssh[t] = g_scale[HH + t]; }
    __syncthreads();
    const int total = EE * (HH / 4);
    float4* p = (float4*)lin;
    for (int i = blockIdx.x * blockDim.x + t; i < total; i += gridDim.x * blockDim.x) {
        int cq = (i & 31) * 4;
        float4 v = p[i];
        v.x = fsilu(fmaf(v.x, ssc[cq + 0], ssh[cq + 0]));
        v.y = fsilu(fmaf(v.y, ssc[cq + 1], ssh[cq + 1]));
        v.z = fsilu(fmaf(v.z, ssc[cq + 2], ssh[cq + 2]));
        v.w = fsilu(fmaf(v.w, ssc[cq + 3], ssh[cq + 3]));
        p[i] = v;
    }
}

// ---- node-centric CSR pass (R3 verified) ----
__global__ __launch_bounds__(128) void k_nodepass(const float* __restrict__ ue) {
    int n = blockIdx.x;
    int c = threadIdx.x;
    int b0 = g_rowptr[n], b1 = g_rowptr[n + 1];
    float agg = 0.f;
    for (int i = b0; i < b1; i++) {
        int e = g_eidx[i];
        agg += fsigmoid(ue[e * HH + c]);
    }
    float inv = 1.f / (agg + EPS_NORM);
    float acc = 0.f;
    for (int i = b0; i < b1; i++) {
        int e = g_eidx[i];
        int d = g_dst32[e];
        float sg = fsigmoid(ue[e * HH + c]);
        acc = fmaf(sg, g_D[d * HH + c], acc);
    }
    g_h[n * HH + c] = g_S[n * HH + c] + acc * inv;
}

// ---------------- final node output ----------------
__global__ void k_nodes_out(const float* __restrict__ nf, float* __restrict__ outN) {
    int i = blockIdx.x * blockDim.x + threadIdx.x;
    if (i >= NN * HH) return;
    int c = i & (HH - 1);
    float x = fmaf(g_h[i], g_scale[2 * HH + c], g_scale[3 * HH + c]);
    outN[i] = nf[i] + fsilu(x);
}

// ---------------- launch ----------------
extern "C" void kernel_launch(void* const* d_in, const int* in_sizes, int n_in,
                              void* d_out, int out_size) {
    const void*  ei = d_in[0];
    const float* nf = (const float*)d_in[1];
    const float* ef = (const float*)d_in[2];
    const float* Wg = (const float*)d_in[3];
    const float* bg = (const float*)d_in[4];
    const float* Ws = (const float*)d_in[5];
    const float* bs = (const float*)d_in[6];
    const float* Wd = (const float*)d_in[7];
    const float* bd = (const float*)d_in[8];
    const float* zg = (const float*)d_in[9];
    const float* zb = (const float*)d_in[10];
    const float* ng = (const float*)d_in[11];
    const float* nb = (const float*)d_in[12];

    float* outN = (float*)d_out;            // [N, H] updated_nodes
    float* lin  = outN + (size_t)NN * HH;   // [E, H] lin -> updated_edge (in place)

    static int s_attr_done = 0;
    if (!s_attr_done) {
        cudaFuncSetAttribute(k_edge_hmma, cudaFuncAttributeMaxDynamicSharedMemorySize, SMEM_TOT2);
        s_attr_done = 1;
    }

    // order chosen so k_edge_hmma is launch index 3 (ncu profiles index 3)
    k_detect<<<1, 256>>>((const int*)ei);                                     // 0
    k_node_gemm<<<dim3((NN + 127) / 128, 4), 256>>>(nf, Wg, bg, Wd, bd, Ws, bs); // 1
    k_wconv<<<(HH * HH + 255) / 256, 256>>>(Wg);                              // 2
    k_edge_hmma<<<EE / 64, 256, SMEM_TOT2>>>(ei, ef, lin);                    // 3  <-- profiled
    k_zero<<<(NN + 255) / 256, 256>>>();                                      // 4
    k_convert_hist<<<(EE + 255) / 256, 256>>>(ei);                            // 5
    k_scan<<<1, 512>>>();                                                     // 6
    k_scatter<<<(EE + 255) / 256, 256>>>();                                   // 7
    k_stats<<<2048, 128>>>(lin, EE, 0, 0);                                    // 8
    k_finalize<<<1, 128>>>(0, 0, zg, zb, (float)EE);                          // 9
    k_edge_bn<<<2048, 256>>>(lin);                                            // 10
    k_nodepass<<<NN, 128>>>(lin);                                             // 11
    k_stats<<<2048, 128>>>(nullptr, NN, 2 * HH, 1);                           // 12
    k_finalize<<<1, 128>>>(2 * HH, 2 * HH, ng, nb, (float)NN);                // 13
    k_nodes_out<<<(NN * HH + 255) / 256, 256>>>(nf, outN);                    // 14
}